// round 2
// baseline (speedup 1.0000x reference)
#include <cuda_runtime.h>
#include <cstdint>

// Problem shape (fixed by reference)
#define Bn 4
#define Cn 64
#define Hn 256
#define Wn 448
#define HW (Hn * Wn)                 // 114688
#define NPIX (Bn * HW)               // 458752
#define PITCH 68                     // 64 channels + 1 norm + 3 pad (272B rows, 16B-aligned)
#define SCRATCH_FLOATS ((size_t)NPIX * PITCH)  // ~125 MB

// Channel-last accumulator: scratch[pix][c], c in [0,64], 65..67 pad.
// Zero-initialized at module load; finalize_kernel re-zeroes the tiles it
// consumes, so the "scratch == 0 on entry" invariant holds for every call.
__device__ __align__(16) float g_scratch[SCRATCH_FLOATS];

// ---------------------------------------------------------------------------
// Kernel 1: bilinear scatter-add with vectorized reductions.
// One thread per source pixel. For each of 4 corners: 16x red.v4.f32 (channels)
// + 1x red.f32 (norm weight).
// ---------------------------------------------------------------------------
__global__ void __launch_bounds__(256) scatter_kernel(
    const float* __restrict__ inp,     // [B, 64, H, W]
    const float* __restrict__ flow,    // [B, 2, H, W]
    const float* __restrict__ metric)  // [B, 1, H, W]
{
    int idx = blockIdx.x * 256 + threadIdx.x;
    if (idx >= NPIX) return;

    int b  = idx / HW;
    int hw = idx - b * HW;
    int y  = hw / Wn;
    int x  = hw - y * Wn;

    float fx = (float)x + __ldg(&flow[(size_t)(b * 2 + 0) * HW + hw]);
    float fy = (float)y + __ldg(&flow[(size_t)(b * 2 + 1) * HW + hw]);
    float m  = __expf(__ldg(&metric[(size_t)b * HW + hw]));

    float x0f = floorf(fx), y0f = floorf(fy);
    int   x0  = (int)x0f,  y0  = (int)y0f;
    float ax  = fx - x0f,  ay  = fy - y0f;   // in [0,1)

    int   xs[4] = { x0, x0 + 1, x0,     x0 + 1 };
    int   ys[4] = { y0, y0,     y0 + 1, y0 + 1 };
    float ws[4] = { (1.f - ax) * (1.f - ay), ax * (1.f - ay),
                    (1.f - ax) * ay,         ax * ay };

    float* bases[4];
    #pragma unroll
    for (int k = 0; k < 4; k++) {
        bool valid = (xs[k] >= 0) & (xs[k] < Wn) & (ys[k] >= 0) & (ys[k] < Hn);
        ws[k] = valid ? ws[k] * m : 0.f;
        int tpix = valid ? (b * HW + ys[k] * Wn + xs[k]) : (b * HW);
        bases[k] = g_scratch + (size_t)tpix * PITCH;   // never dereferenced when ws==0
    }

    const float* ip = inp + (size_t)b * Cn * HW + hw;

    #pragma unroll
    for (int c4 = 0; c4 < 16; c4++) {
        float v0 = __ldg(&ip[(size_t)(c4 * 4 + 0) * HW]);
        float v1 = __ldg(&ip[(size_t)(c4 * 4 + 1) * HW]);
        float v2 = __ldg(&ip[(size_t)(c4 * 4 + 2) * HW]);
        float v3 = __ldg(&ip[(size_t)(c4 * 4 + 3) * HW]);
        #pragma unroll
        for (int k = 0; k < 4; k++) {
            float w = ws[k];
            if (w != 0.f) {
                asm volatile(
                    "red.global.add.v4.f32 [%0], {%1, %2, %3, %4};"
                    :: "l"(bases[k] + c4 * 4),
                       "f"(v0 * w), "f"(v1 * w), "f"(v2 * w), "f"(v3 * w)
                    : "memory");
            }
        }
    }

    #pragma unroll
    for (int k = 0; k < 4; k++) {
        float w = ws[k];
        if (w != 0.f) {
            asm volatile("red.global.add.f32 [%0], %1;"
                         :: "l"(bases[k] + 64), "f"(w) : "memory");
        }
    }
}

// ---------------------------------------------------------------------------
// Kernel 2: normalize + transpose scratch (B*HW, 68) -> out (B,64,H,W),
// then zero the scratch tile for the next graph replay.
// One block per 32-pixel tile (tiles never cross a batch boundary since
// HW % 32 == 0). Coalesced float4 reads, coalesced channel-major writes.
// smem pitch 69 (odd) avoids bank conflicts on the transposed reads.
// ---------------------------------------------------------------------------
__global__ void __launch_bounds__(256) finalize_kernel(float* __restrict__ out) {
    __shared__ float s[32 * 69];
    int tile = blockIdx.x;
    size_t gbase = (size_t)tile * 32 * PITCH;
    float4* g4 = reinterpret_cast<float4*>(g_scratch + gbase);
    const int N4 = 32 * PITCH / 4;   // 544 float4 per tile; 17 per pixel

    for (int i4 = threadIdx.x; i4 < N4; i4 += 256) {
        float4 v = g4[i4];
        int p = i4 / 17;
        int c = (i4 - p * 17) * 4;
        float* sp = s + p * 69 + c;
        sp[0] = v.x; sp[1] = v.y; sp[2] = v.z; sp[3] = v.w;
    }
    __syncthreads();

    // Re-zero scratch tile for the next replay (lines are L2-hot from the read).
    const float4 z4 = make_float4(0.f, 0.f, 0.f, 0.f);
    for (int i4 = threadIdx.x; i4 < N4; i4 += 256) {
        g4[i4] = z4;
    }

    int p  = threadIdx.x & 31;     // pixel within tile
    int cb = threadIdx.x >> 5;     // channel block 0..7
    float norm = s[p * 69 + 64];
    float rn = (norm == 0.f) ? 1.f : (1.f / norm);

    int pix = tile * 32 + p;
    int b   = pix / HW;
    int hw  = pix - b * HW;
    float* ob = out + (size_t)b * Cn * HW + hw;

    #pragma unroll
    for (int j = 0; j < 8; j++) {
        int c = cb * 8 + j;
        ob[(size_t)c * HW] = s[p * 69 + c] * rn;
    }
}

// ---------------------------------------------------------------------------
extern "C" void kernel_launch(void* const* d_in, const int* in_sizes, int n_in,
                              void* d_out, int out_size) {
    const float* inp    = (const float*)d_in[0];
    const float* flow   = (const float*)d_in[1];
    const float* metric = (const float*)d_in[2];
    float* out = (float*)d_out;

    scatter_kernel<<<(NPIX + 255) / 256, 256>>>(inp, flow, metric);
    finalize_kernel<<<NPIX / 32, 256>>>(out);
}

// round 3
// speedup vs baseline: 1.8960x; 1.8960x over previous
#include <cuda_runtime.h>
#include <cstdint>

// Problem shape (fixed by reference)
#define Bn 4
#define Cn 64
#define Hn 256
#define Wn 448
#define HW (Hn * Wn)                 // 114688
#define NPIX (Bn * HW)               // 458752
#define PITCH 68                     // 64 ch + 1 norm + 3 pad (272B rows, 16B-aligned)
#define SCRATCH_FLOATS ((size_t)NPIX * PITCH)  // ~125 MB

#define PIX_PER_BLK 64               // 64 | Wn=448 -> a group never crosses a row
#define GRID_SCATTER (NPIX / PIX_PER_BLK)     // 7168

// Channel-last accumulator: scratch[pix][c], c in [0,64], 65..67 pad.
// Zero-initialized at module load; finalize_kernel re-zeroes the tiles it
// consumes, so "scratch == 0 on entry" holds for every graph replay.
__device__ __align__(16) float g_scratch[SCRATCH_FLOATS];

// ---------------------------------------------------------------------------
// Kernel 1: bilinear scatter-add, warp-coalesced atomics.
// Block = 256 threads / 64 consecutive pixels (same image row).
// Phase 1: coalesced LDG of the 64x64 channel tile -> smem (fused transpose).
// Phase 2: half-warp per pixel; lane ll covers channels 4ll..4ll+3, so each
//          red.v4 instruction spans one contiguous 256B pixel-corner row.
// Epilogue: one scalar norm-RED per (pixel, corner).
// ---------------------------------------------------------------------------
__global__ void __launch_bounds__(256) scatter_kernel(
    const float* __restrict__ inp,     // [B, 64, H, W]
    const float* __restrict__ flow,    // [B, 2, H, W]
    const float* __restrict__ metric)  // [B, 1, H, W]
{
    __shared__ float s_in[PIX_PER_BLK * PITCH];   // 64 rows x 68 floats (17.4 KB)
    __shared__ float s_fx[PIX_PER_BLK];
    __shared__ float s_fy[PIX_PER_BLK];
    __shared__ float s_m [PIX_PER_BLK];

    const int blk  = blockIdx.x;
    const int b    = blk / (HW / PIX_PER_BLK);
    const int hw0  = (blk % (HW / PIX_PER_BLK)) * PIX_PER_BLK;
    const int y    = hw0 / Wn;          // whole group shares this row
    const int x0b  = hw0 - y * Wn;

    // ---- Phase 1: stage inputs ----
    {
        const float* ib = inp + (size_t)b * Cn * HW + hw0;
        #pragma unroll
        for (int i = threadIdx.x; i < Cn * PIX_PER_BLK; i += 256) {
            int c = i >> 6;            // 0..63
            int p = i & 63;            // 0..63  (consecutive threads -> coalesced)
            s_in[p * PITCH + c] = __ldg(&ib[(size_t)c * HW + p]);
        }
        if (threadIdx.x < PIX_PER_BLK) {
            int p = threadIdx.x;
            s_fx[p] = (float)(x0b + p) + __ldg(&flow[(size_t)(b * 2 + 0) * HW + hw0 + p]);
            s_fy[p] = (float)y         + __ldg(&flow[(size_t)(b * 2 + 1) * HW + hw0 + p]);
            s_m [p] = __expf(__ldg(&metric[(size_t)b * HW + hw0 + p]));
        }
    }
    __syncthreads();

    // ---- Phase 2: coalesced channel REDs ----
    {
        const int lane = threadIdx.x & 31;
        const int warp = threadIdx.x >> 5;
        const int half = lane >> 4;        // 0 or 1
        const int ll   = lane & 15;        // channel quad index

        #pragma unroll
        for (int j = 0; j < 4; j++) {
            int p = warp * 8 + j * 2 + half;

            float fx = s_fx[p], fy = s_fy[p], m = s_m[p];
            float x0f = floorf(fx), y0f = floorf(fy);
            int   cx0 = (int)x0f,  cy0 = (int)y0f;
            float ax  = fx - x0f,  ay  = fy - y0f;

            int   xs[4] = { cx0, cx0 + 1, cx0,     cx0 + 1 };
            int   ys[4] = { cy0, cy0,     cy0 + 1, cy0 + 1 };
            float ws[4] = { (1.f - ax) * (1.f - ay), ax * (1.f - ay),
                            (1.f - ax) * ay,         ax * ay };

            float4 v = *reinterpret_cast<const float4*>(s_in + p * PITCH + ll * 4);

            #pragma unroll
            for (int k = 0; k < 4; k++) {
                bool valid = (xs[k] >= 0) & (xs[k] < Wn) & (ys[k] >= 0) & (ys[k] < Hn);
                float w = valid ? ws[k] * m : 0.f;
                if (w != 0.f) {
                    size_t tpix = (size_t)b * HW + (size_t)ys[k] * Wn + xs[k];
                    float* dst = g_scratch + tpix * PITCH + ll * 4;
                    asm volatile(
                        "red.global.add.v4.f32 [%0], {%1, %2, %3, %4};"
                        :: "l"(dst),
                           "f"(v.x * w), "f"(v.y * w), "f"(v.z * w), "f"(v.w * w)
                        : "memory");
                }
            }
        }
    }

    // ---- Epilogue: norm-channel REDs, one (pixel,corner) per thread ----
    {
        int p = threadIdx.x >> 2;          // 0..63
        int k = threadIdx.x & 3;           // corner

        float fx = s_fx[p], fy = s_fy[p], m = s_m[p];
        float x0f = floorf(fx), y0f = floorf(fy);
        int   cx0 = (int)x0f,  cy0 = (int)y0f;
        float ax  = fx - x0f,  ay  = fy - y0f;

        int   xk = cx0 + (k & 1);
        int   yk = cy0 + (k >> 1);
        float wx = (k & 1)  ? ax : (1.f - ax);
        float wy = (k >> 1) ? ay : (1.f - ay);
        bool valid = (xk >= 0) & (xk < Wn) & (yk >= 0) & (yk < Hn);
        float w = valid ? wx * wy * m : 0.f;
        if (w != 0.f) {
            size_t tpix = (size_t)b * HW + (size_t)yk * Wn + xk;
            asm volatile("red.global.add.f32 [%0], %1;"
                         :: "l"(g_scratch + tpix * PITCH + 64), "f"(w) : "memory");
        }
    }
}

// ---------------------------------------------------------------------------
// Kernel 2: normalize + transpose scratch (B*HW, 68) -> out (B,64,H,W),
// then zero the scratch tile for the next graph replay.
// ---------------------------------------------------------------------------
__global__ void __launch_bounds__(256) finalize_kernel(float* __restrict__ out) {
    __shared__ float s[32 * 69];
    int tile = blockIdx.x;
    size_t gbase = (size_t)tile * 32 * PITCH;
    float4* g4 = reinterpret_cast<float4*>(g_scratch + gbase);
    const int N4 = 32 * PITCH / 4;   // 544 float4 per tile; 17 per pixel

    for (int i4 = threadIdx.x; i4 < N4; i4 += 256) {
        float4 v = g4[i4];
        int p = i4 / 17;
        int c = (i4 - p * 17) * 4;
        float* sp = s + p * 69 + c;
        sp[0] = v.x; sp[1] = v.y; sp[2] = v.z; sp[3] = v.w;
    }
    __syncthreads();

    // Re-zero scratch tile for the next replay (lines are L2-hot from the read).
    const float4 z4 = make_float4(0.f, 0.f, 0.f, 0.f);
    for (int i4 = threadIdx.x; i4 < N4; i4 += 256) {
        g4[i4] = z4;
    }

    int p  = threadIdx.x & 31;     // pixel within tile
    int cb = threadIdx.x >> 5;     // channel block 0..7
    float norm = s[p * 69 + 64];
    float rn = (norm == 0.f) ? 1.f : (1.f / norm);

    int pix = tile * 32 + p;
    int b   = pix / HW;
    int hw  = pix - b * HW;
    float* ob = out + (size_t)b * Cn * HW + hw;

    #pragma unroll
    for (int j = 0; j < 8; j++) {
        int c = cb * 8 + j;
        ob[(size_t)c * HW] = s[p * 69 + c] * rn;
    }
}

// ---------------------------------------------------------------------------
extern "C" void kernel_launch(void* const* d_in, const int* in_sizes, int n_in,
                              void* d_out, int out_size) {
    const float* inp    = (const float*)d_in[0];
    const float* flow   = (const float*)d_in[1];
    const float* metric = (const float*)d_in[2];
    float* out = (float*)d_out;

    scatter_kernel<<<GRID_SCATTER, 256>>>(inp, flow, metric);
    finalize_kernel<<<NPIX / 32, 256>>>(out);
}